// round 6
// baseline (speedup 1.0000x reference)
#include <cuda_runtime.h>

#define N_NODES 100000
#define N_EDGES 1600000
#define D 64
#define N_LAYERS 5
#define N_GRAPHS 256
#define N_RS (N_NODES + 1)
#define SCAN_B 1024
#define NB ((N_RS + SCAN_B - 1) / SCAN_B)   // 98

typedef unsigned long long ull;

// ---------------- device scratch (static: no allocation at runtime) --------
__device__ float g_bufA[N_NODES * D];
__device__ float g_bufB[N_NODES * D];
__device__ int   g_srcs[N_EDGES];       // src sorted by dst (CSR payload)
__device__ int   g_batch[N_NODES];
__device__ int   g_rowstart[N_RS];
__device__ int   g_cursor[N_NODES];
__device__ int   g_bsum[NB];
__device__ float g_pool[N_GRAPHS * D];
__device__ float g_cnt[N_GRAPHS];
__device__ int   g_flags[2];            // [0]=edge_index is int64, [1]=batch is int64

// ---------------- packed fp32x2 helpers (Blackwell) -------------------------
__device__ __forceinline__ ull f32x2_fma(ull a, ull b, ull c) {
    ull d;
    asm("fma.rn.f32x2 %0, %1, %2, %3;" : "=l"(d) : "l"(a), "l"(b), "l"(c));
    return d;
}
__device__ __forceinline__ ull f32_dup(float v) {
    ull d;
    asm("mov.b64 %0, {%1, %1};" : "=l"(d) : "f"(v));
    return d;
}
__device__ __forceinline__ void f32x2_unpack(ull a, float& lo, float& hi) {
    asm("mov.b64 {%0, %1}, %2;" : "=f"(lo), "=f"(hi) : "l"(a));
}

// ---------------- dtype detection (int64 vs int32) -------------------------
// int64 values < 2^32 -> every odd 32-bit word is 0.
__global__ void detect_kernel(const void* ep, const void* bp) {
    __shared__ int ez, bz;
    if (threadIdx.x == 0) { ez = 0; bz = 0; }
    __syncthreads();
    const int* ew = (const int*)ep;
    if (ew[2 * threadIdx.x + 1] != 0) atomicOr(&ez, 1);
    const int* bw = (const int*)bp;
    if (bw[50001 + 2 * threadIdx.x] != 0) atomicOr(&bz, 1);
    __syncthreads();
    if (threadIdx.x == 0) { g_flags[0] = ez ? 0 : 1; g_flags[1] = bz ? 0 : 1; }
}

__global__ void conv_batch_kernel(const void* p) {
    int i = blockIdx.x * blockDim.x + threadIdx.x;
    if (i >= N_NODES) return;
    g_batch[i] = g_flags[1] ? (int)((const long long*)p)[i] : ((const int*)p)[i];
}

// ---------------- CSR build -------------------------------------------------
__global__ void zero_meta_kernel() {
    int i = blockIdx.x * blockDim.x + threadIdx.x;
    if (i < N_RS)          g_rowstart[i] = 0;
    if (i < N_GRAPHS * D)  g_pool[i] = 0.f;
    if (i < N_GRAPHS)      g_cnt[i] = 0.f;
}

__global__ void hist_kernel(const void* p) {
    int e = blockIdx.x * blockDim.x + threadIdx.x;
    if (e >= N_EDGES) return;
    int d = g_flags[0] ? (int)((const long long*)p)[N_EDGES + e]
                       : ((const int*)p)[N_EDGES + e];
    atomicAdd(&g_rowstart[d + 1], 1);
}

__global__ __launch_bounds__(SCAN_B) void scan1_kernel() {
    __shared__ int sm[SCAN_B];
    int i = blockIdx.x * SCAN_B + threadIdx.x;
    sm[threadIdx.x] = (i < N_RS) ? g_rowstart[i] : 0;
    __syncthreads();
    for (int off = 1; off < SCAN_B; off <<= 1) {
        int t = 0;
        if ((int)threadIdx.x >= off) t = sm[threadIdx.x - off];
        __syncthreads();
        sm[threadIdx.x] += t;
        __syncthreads();
    }
    if (i < N_RS) g_rowstart[i] = sm[threadIdx.x];
    if (threadIdx.x == SCAN_B - 1) g_bsum[blockIdx.x] = sm[SCAN_B - 1];
}

__global__ void scan2_kernel() {
    __shared__ int s[128];
    int t = threadIdx.x;
    s[t] = (t < NB) ? g_bsum[t] : 0;
    __syncthreads();
    if (t == 0) {
        int run = 0;
        for (int i = 0; i < NB; i++) { int v = s[i]; s[i] = run; run += v; }
    }
    __syncthreads();
    if (t < NB) g_bsum[t] = s[t];
}

__global__ __launch_bounds__(SCAN_B) void scan3_kernel() {
    int i = blockIdx.x * SCAN_B + threadIdx.x;
    if (i < N_RS) g_rowstart[i] += g_bsum[blockIdx.x];
}

__global__ void cursor_kernel() {
    int i = blockIdx.x * blockDim.x + threadIdx.x;
    if (i < N_NODES) g_cursor[i] = g_rowstart[i];
}

__global__ void fill_kernel(const void* p) {
    int e = blockIdx.x * blockDim.x + threadIdx.x;
    if (e >= N_EDGES) return;
    int s, d;
    if (g_flags[0]) {
        const long long* q = (const long long*)p;
        s = (int)q[e]; d = (int)q[N_EDGES + e];
    } else {
        const int* q = (const int*)p;
        s = q[e]; d = q[N_EDGES + e];
    }
    int pos = atomicAdd(&g_cursor[d], 1);
    g_srcs[pos] = s;
}

// ---------------- 64x64 register-blocked GEMM tile (packed f32x2) -----------
// out[i][j] = sum_k sZ[r0+i][k] * sW[k][tx*4+j]
__device__ __forceinline__ void gemm_tile(const float* __restrict__ sZ,
                                          const float* __restrict__ sW,
                                          int r0, int tx, float out[4][4]) {
    ull acc[4][2];
#pragma unroll
    for (int i = 0; i < 4; i++) { acc[i][0] = 0ull; acc[i][1] = 0ull; }
#pragma unroll
    for (int k0 = 0; k0 < 64; k0 += 4) {
        float4 zq[4];
#pragma unroll
        for (int i = 0; i < 4; i++)
            zq[i] = *(const float4*)(sZ + (r0 + i) * 64 + k0);
#pragma unroll
        for (int k = 0; k < 4; k++) {
            ulonglong2 wv = *(const ulonglong2*)(sW + (k0 + k) * 64 + (tx << 2));
#pragma unroll
            for (int i = 0; i < 4; i++) {
                float zk = (k == 0) ? zq[i].x : (k == 1) ? zq[i].y
                         : (k == 2) ? zq[i].z : zq[i].w;
                ull zd = f32_dup(zk);
                acc[i][0] = f32x2_fma(zd, wv.x, acc[i][0]);
                acc[i][1] = f32x2_fma(zd, wv.y, acc[i][1]);
            }
        }
    }
#pragma unroll
    for (int i = 0; i < 4; i++) {
        f32x2_unpack(acc[i][0], out[i][0], out[i][1]);
        f32x2_unpack(acc[i][1], out[i][2], out[i][3]);
    }
}

// ---------------- fused GIN layer: z = h + agg(h); out = relu(z@W1+b1)@W2+b2
__global__ __launch_bounds__(256) void layer_kernel(
    const float* __restrict__ h_in, float* __restrict__ h_out,
    const float* __restrict__ W1, const float* __restrict__ b1,
    const float* __restrict__ W2, const float* __restrict__ b2) {
    __shared__ float sZ[64 * 64];   // z tile [r][k]; reused for hidden act
    __shared__ float sW[64 * 64];   // weights [k][c]
    int tid = threadIdx.x;
    int row0 = blockIdx.x * 64;

    // preload W1 (coalesced float4)
#pragma unroll
    for (int j = 0; j < 4; j++) {
        int idx = (j * 256 + tid) * 4;
        *(float4*)(sW + idx) = *(const float4*)(W1 + idx);
    }

    // Phase A: aggregate. 4 groups of 64 threads; thread owns column c.
    {
        int g = tid >> 6, c = tid & 63;
#pragma unroll 1
        for (int j = 0; j < 16; j++) {
            int nl = g * 16 + j;
            int node = row0 + nl;
            float acc = 0.f;
            if (node < N_NODES) {
                acc = h_in[node * 64 + c];
                int s = g_rowstart[node];
                int e = g_rowstart[node + 1];
                int i = s;
                for (; i + 4 <= e; i += 4) {
                    int s0 = g_srcs[i], s1 = g_srcs[i + 1];
                    int s2 = g_srcs[i + 2], s3 = g_srcs[i + 3];
                    float v0 = __ldg(&h_in[s0 * 64 + c]);
                    float v1 = __ldg(&h_in[s1 * 64 + c]);
                    float v2 = __ldg(&h_in[s2 * 64 + c]);
                    float v3 = __ldg(&h_in[s3 * 64 + c]);
                    acc += v0; acc += v1; acc += v2; acc += v3;
                }
                for (; i < e; i++) acc += __ldg(&h_in[g_srcs[i] * 64 + c]);
            }
            sZ[nl * 64 + c] = acc;
        }
    }
    __syncthreads();

    // Phase B: GEMM1 + bias + relu
    int ty = tid >> 4, tx = tid & 15;
    int r0 = ty << 2;
    float res[4][4];
    gemm_tile(sZ, sW, r0, tx, res);
    float4 bv1 = *(const float4*)(b1 + (tx << 2));
    __syncthreads();   // all reads of sZ/sW done
#pragma unroll
    for (int i = 0; i < 4; i++) {
        float4 v;
        v.x = fmaxf(res[i][0] + bv1.x, 0.f);
        v.y = fmaxf(res[i][1] + bv1.y, 0.f);
        v.z = fmaxf(res[i][2] + bv1.z, 0.f);
        v.w = fmaxf(res[i][3] + bv1.w, 0.f);
        *(float4*)(sZ + (r0 + i) * 64 + (tx << 2)) = v;
    }
#pragma unroll
    for (int j = 0; j < 4; j++) {
        int idx = (j * 256 + tid) * 4;
        *(float4*)(sW + idx) = *(const float4*)(W2 + idx);
    }
    __syncthreads();

    // Phase C: GEMM2 + bias, store
    gemm_tile(sZ, sW, r0, tx, res);
    float4 bv2 = *(const float4*)(b2 + (tx << 2));
#pragma unroll
    for (int i = 0; i < 4; i++) {
        int r = row0 + r0 + i;
        if (r < N_NODES) {
            float4 v;
            v.x = res[i][0] + bv2.x;
            v.y = res[i][1] + bv2.y;
            v.z = res[i][2] + bv2.z;
            v.w = res[i][3] + bv2.w;
            *(float4*)(h_out + r * 64 + (tx << 2)) = v;
        }
    }
}

// ---------------- mean pool (batch is sorted -> run-length compress atomics)
__global__ __launch_bounds__(256) void pool_kernel(const float* __restrict__ h) {
    const int NPG = 8;
    int grp = blockIdx.x * 4 + (threadIdx.x >> 6);
    int c = threadIdx.x & 63;
    int i0 = grp * NPG;
    if (i0 >= N_NODES) return;
    float acc = 0.f; int cur = -1; int run = 0;
    for (int j = 0; j < NPG; j++) {
        int i = i0 + j;
        if (i >= N_NODES) break;
        int b = g_batch[i];
        if (b != cur) {
            if (cur >= 0) {
                atomicAdd(&g_pool[cur * 64 + c], acc);
                if (c == 0) atomicAdd(&g_cnt[cur], (float)run);
            }
            acc = 0.f; cur = b; run = 0;
        }
        acc += h[i * 64 + c];
        run++;
    }
    if (cur >= 0) {
        atomicAdd(&g_pool[cur * 64 + c], acc);
        if (c == 0) atomicAdd(&g_cnt[cur], (float)run);
    }
}

// ---------------- readout MLP ----------------------------------------------
__global__ __launch_bounds__(64) void readout_kernel(
    const float* __restrict__ mW1, const float* __restrict__ mb1,
    const float* __restrict__ mW2, const float* __restrict__ mb2,
    float* __restrict__ out) {
    __shared__ float p[64], t[64];
    int g = blockIdx.x, c = threadIdx.x;
    float cnt = g_cnt[g];
    if (cnt < 1.f) cnt = 1.f;
    p[c] = g_pool[g * 64 + c] / cnt;
    __syncthreads();
    float a = mb1[c];
#pragma unroll 8
    for (int k = 0; k < 64; k++) a += p[k] * mW1[k * 64 + c];
    t[c] = a > 0.f ? a : 0.f;
    __syncthreads();
    float o = mb2[c];
#pragma unroll 8
    for (int k = 0; k < 64; k++) o += t[k] * mW2[k * 64 + c];
    out[g * 64 + c] = o;
}

// ---------------- launch ----------------------------------------------------
extern "C" void kernel_launch(void* const* d_in, const int* in_sizes, int n_in,
                              void* d_out, int out_size) {
    const float* x   = (const float*)d_in[0];
    const void*  ei  = d_in[1];
    const void*  ba  = d_in[2];
    const float* Ws1 = (const float*)d_in[3];
    const float* bs1 = (const float*)d_in[4];
    const float* Ws2 = (const float*)d_in[5];
    const float* bs2 = (const float*)d_in[6];
    const float* mW1 = (const float*)d_in[7];
    const float* mb1 = (const float*)d_in[8];
    const float* mW2 = (const float*)d_in[9];
    const float* mb2 = (const float*)d_in[10];
    float* out = (float*)d_out;

    float *bufA, *bufB;
    cudaGetSymbolAddress((void**)&bufA, g_bufA);
    cudaGetSymbolAddress((void**)&bufB, g_bufB);

    const int EG = (N_EDGES + 255) / 256;   // 6250
    const int NG = (N_NODES + 255) / 256;   // 391
    const int LG = (N_NODES + 63) / 64;     // 1563

    detect_kernel<<<1, 256>>>(ei, ba);
    conv_batch_kernel<<<NG, 256>>>(ba);
    zero_meta_kernel<<<(N_RS + 255) / 256, 256>>>();
    hist_kernel<<<EG, 256>>>(ei);
    scan1_kernel<<<NB, SCAN_B>>>();
    scan2_kernel<<<1, 128>>>();
    scan3_kernel<<<NB, SCAN_B>>>();
    cursor_kernel<<<NG, 256>>>();
    fill_kernel<<<EG, 256>>>(ei);

    // ping-pong: x->A->B->A->B->A
    layer_kernel<<<LG, 256>>>(x,    bufA, Ws1 + 0 * D * D, bs1 + 0 * D, Ws2 + 0 * D * D, bs2 + 0 * D);
    layer_kernel<<<LG, 256>>>(bufA, bufB, Ws1 + 1 * D * D, bs1 + 1 * D, Ws2 + 1 * D * D, bs2 + 1 * D);
    layer_kernel<<<LG, 256>>>(bufB, bufA, Ws1 + 2 * D * D, bs1 + 2 * D, Ws2 + 2 * D * D, bs2 + 2 * D);
    layer_kernel<<<LG, 256>>>(bufA, bufB, Ws1 + 3 * D * D, bs1 + 3 * D, Ws2 + 3 * D * D, bs2 + 3 * D);
    layer_kernel<<<LG, 256>>>(bufB, bufA, Ws1 + 4 * D * D, bs1 + 4 * D, Ws2 + 4 * D * D, bs2 + 4 * D);

    pool_kernel<<<(N_NODES / 8 + 3) / 4, 256>>>(bufA);
    readout_kernel<<<N_GRAPHS, 64>>>(mW1, mb1, mW2, mb2, out);
}

// round 8
// speedup vs baseline: 1.3549x; 1.3549x over previous
#include <cuda_runtime.h>

#define N_NODES 100000
#define N_EDGES 1600000
#define D 64
#define N_LAYERS 5
#define N_GRAPHS 256
#define N_RS (N_NODES + 1)
#define SCAN_B 1024
#define NB ((N_RS + SCAN_B - 1) / SCAN_B)   // 98

typedef unsigned long long ull;

// ---------------- device scratch (static: no allocation at runtime) --------
__device__ float g_bufA[N_NODES * D];
__device__ float g_bufB[N_NODES * D];
__device__ int   g_srcs[N_EDGES];       // src sorted by dst (CSR payload)
__device__ int   g_batch[N_NODES];
__device__ int   g_rowstart[N_RS];
__device__ int   g_cursor[N_NODES];
__device__ int   g_bsum[NB];
__device__ float g_pool[N_GRAPHS * D];
__device__ float g_cnt[N_GRAPHS];
__device__ int   g_flags[2];            // [0]=edge_index is int64, [1]=batch is int64

// ---------------- packed fp32x2 helpers (Blackwell) -------------------------
__device__ __forceinline__ ull f32x2_fma(ull a, ull b, ull c) {
    ull d;
    asm("fma.rn.f32x2 %0, %1, %2, %3;" : "=l"(d) : "l"(a), "l"(b), "l"(c));
    return d;
}
__device__ __forceinline__ ull f32_dup(float v) {
    ull d;
    asm("mov.b64 %0, {%1, %1};" : "=l"(d) : "f"(v));
    return d;
}
__device__ __forceinline__ void f32x2_unpack(ull a, float& lo, float& hi) {
    asm("mov.b64 {%0, %1}, %2;" : "=f"(lo), "=f"(hi) : "l"(a));
}

// ---------------- dtype detection (int64 vs int32) -------------------------
// int64 values < 2^32 -> every odd 32-bit word is 0.
__global__ void detect_kernel(const void* ep, const void* bp) {
    __shared__ int ez, bz;
    if (threadIdx.x == 0) { ez = 0; bz = 0; }
    __syncthreads();
    const int* ew = (const int*)ep;
    if (ew[2 * threadIdx.x + 1] != 0) atomicOr(&ez, 1);
    const int* bw = (const int*)bp;
    if (bw[50001 + 2 * threadIdx.x] != 0) atomicOr(&bz, 1);
    __syncthreads();
    if (threadIdx.x == 0) { g_flags[0] = ez ? 0 : 1; g_flags[1] = bz ? 0 : 1; }
}

__global__ void conv_batch_kernel(const void* p) {
    int i = blockIdx.x * blockDim.x + threadIdx.x;
    if (i >= N_NODES) return;
    g_batch[i] = g_flags[1] ? (int)((const long long*)p)[i] : ((const int*)p)[i];
}

// ---------------- CSR build -------------------------------------------------
__global__ void zero_meta_kernel() {
    int i = blockIdx.x * blockDim.x + threadIdx.x;
    if (i < N_RS)          g_rowstart[i] = 0;
    if (i < N_GRAPHS * D)  g_pool[i] = 0.f;
    if (i < N_GRAPHS)      g_cnt[i] = 0.f;
}

__global__ void hist_kernel(const void* p) {
    int e = blockIdx.x * blockDim.x + threadIdx.x;
    if (e >= N_EDGES) return;
    int d = g_flags[0] ? (int)((const long long*)p)[N_EDGES + e]
                       : ((const int*)p)[N_EDGES + e];
    atomicAdd(&g_rowstart[d + 1], 1);
}

__global__ __launch_bounds__(SCAN_B) void scan1_kernel() {
    __shared__ int sm[SCAN_B];
    int i = blockIdx.x * SCAN_B + threadIdx.x;
    sm[threadIdx.x] = (i < N_RS) ? g_rowstart[i] : 0;
    __syncthreads();
    for (int off = 1; off < SCAN_B; off <<= 1) {
        int t = 0;
        if ((int)threadIdx.x >= off) t = sm[threadIdx.x - off];
        __syncthreads();
        sm[threadIdx.x] += t;
        __syncthreads();
    }
    if (i < N_RS) g_rowstart[i] = sm[threadIdx.x];
    if (threadIdx.x == SCAN_B - 1) g_bsum[blockIdx.x] = sm[SCAN_B - 1];
}

__global__ void scan2_kernel() {
    __shared__ int s[128];
    int t = threadIdx.x;
    s[t] = (t < NB) ? g_bsum[t] : 0;
    __syncthreads();
    if (t == 0) {
        int run = 0;
        for (int i = 0; i < NB; i++) { int v = s[i]; s[i] = run; run += v; }
    }
    __syncthreads();
    if (t < NB) g_bsum[t] = s[t];
}

__global__ __launch_bounds__(SCAN_B) void scan3_kernel() {
    int i = blockIdx.x * SCAN_B + threadIdx.x;
    if (i < N_RS) g_rowstart[i] += g_bsum[blockIdx.x];
}

__global__ void cursor_kernel() {
    int i = blockIdx.x * blockDim.x + threadIdx.x;
    if (i < N_NODES) g_cursor[i] = g_rowstart[i];
}

__global__ void fill_kernel(const void* p) {
    int e = blockIdx.x * blockDim.x + threadIdx.x;
    if (e >= N_EDGES) return;
    int s, d;
    if (g_flags[0]) {
        const long long* q = (const long long*)p;
        s = (int)q[e]; d = (int)q[N_EDGES + e];
    } else {
        const int* q = (const int*)p;
        s = q[e]; d = q[N_EDGES + e];
    }
    int pos = atomicAdd(&g_cursor[d], 1);
    g_srcs[pos] = s;
}

// ---------------- GIN aggregation: z[i] = h[i] + sum_{e in CSR(i)} h[src[e]]
// 16 threads per node, float4 (LDG.128) gathers. grid covers 16 nodes/block.
__global__ __launch_bounds__(256) void agg_kernel(const float4* __restrict__ h4,
                                                  float4* __restrict__ z4) {
    int node = blockIdx.x * 16 + (threadIdx.x >> 4);
    int c = threadIdx.x & 15;
    if (node >= N_NODES) return;
    float4 acc = h4[node * 16 + c];
    int s = g_rowstart[node];
    int e = g_rowstart[node + 1];
    int i = s;
    for (; i + 2 <= e; i += 2) {
        int s0 = g_srcs[i], s1 = g_srcs[i + 1];
        float4 v0 = __ldg(&h4[s0 * 16 + c]);
        float4 v1 = __ldg(&h4[s1 * 16 + c]);
        acc.x += v0.x; acc.y += v0.y; acc.z += v0.z; acc.w += v0.w;
        acc.x += v1.x; acc.y += v1.y; acc.z += v1.z; acc.w += v1.w;
    }
    if (i < e) {
        float4 v = __ldg(&h4[g_srcs[i] * 16 + c]);
        acc.x += v.x; acc.y += v.y; acc.z += v.z; acc.w += v.w;
    }
    z4[node * 16 + c] = acc;
}

// ---------------- 64x64 register-blocked GEMM tile (packed f32x2) -----------
// out[i][j] = sum_k sZ[r0+i][k] * sW[k][tx*4+j]
__device__ __forceinline__ void gemm_tile(const float* __restrict__ sZ,
                                          const float* __restrict__ sW,
                                          int r0, int tx, float out[4][4]) {
    ull acc[4][2];
#pragma unroll
    for (int i = 0; i < 4; i++) { acc[i][0] = 0ull; acc[i][1] = 0ull; }
#pragma unroll
    for (int k0 = 0; k0 < 64; k0 += 4) {
        float4 zq[4];
#pragma unroll
        for (int i = 0; i < 4; i++)
            zq[i] = *(const float4*)(sZ + (r0 + i) * 64 + k0);
#pragma unroll
        for (int k = 0; k < 4; k++) {
            ulonglong2 wv = *(const ulonglong2*)(sW + (k0 + k) * 64 + (tx << 2));
#pragma unroll
            for (int i = 0; i < 4; i++) {
                float zk = (k == 0) ? zq[i].x : (k == 1) ? zq[i].y
                         : (k == 2) ? zq[i].z : zq[i].w;
                ull zd = f32_dup(zk);
                acc[i][0] = f32x2_fma(zd, wv.x, acc[i][0]);
                acc[i][1] = f32x2_fma(zd, wv.y, acc[i][1]);
            }
        }
    }
#pragma unroll
    for (int i = 0; i < 4; i++) {
        f32x2_unpack(acc[i][0], out[i][0], out[i][1]);
        f32x2_unpack(acc[i][1], out[i][2], out[i][3]);
    }
}

// ---------------- fused MLP: out = relu(z@W1 + b1) @ W2 + b2 ---------------
__global__ __launch_bounds__(256) void mlp_kernel(
    const float* __restrict__ z, float* __restrict__ out,
    const float* __restrict__ W1, const float* __restrict__ b1,
    const float* __restrict__ W2, const float* __restrict__ b2) {
    __shared__ float sZ[64 * 64];   // z tile [r][k]; reused for hidden act
    __shared__ float sW[64 * 64];   // weights [k][c]
    int tid = threadIdx.x;
    int row0 = blockIdx.x * 64;

    // load z tile (coalesced float4; zero-pad tail rows)
#pragma unroll
    for (int j = 0; j < 4; j++) {
        int idx = (j * 256 + tid) * 4;
        int r = idx >> 6;
        if (row0 + r < N_NODES)
            *(float4*)(sZ + idx) = *(const float4*)(z + row0 * 64 + idx);
        else
            *(float4*)(sZ + idx) = make_float4(0.f, 0.f, 0.f, 0.f);
    }
#pragma unroll
    for (int j = 0; j < 4; j++) {
        int idx = (j * 256 + tid) * 4;
        *(float4*)(sW + idx) = *(const float4*)(W1 + idx);
    }
    __syncthreads();

    int ty = tid >> 4, tx = tid & 15;
    int r0 = ty << 2;
    float res[4][4];
    gemm_tile(sZ, sW, r0, tx, res);
    float4 bv1 = *(const float4*)(b1 + (tx << 2));
    __syncthreads();   // all reads of sZ/sW done
#pragma unroll
    for (int i = 0; i < 4; i++) {
        float4 v;
        v.x = fmaxf(res[i][0] + bv1.x, 0.f);
        v.y = fmaxf(res[i][1] + bv1.y, 0.f);
        v.z = fmaxf(res[i][2] + bv1.z, 0.f);
        v.w = fmaxf(res[i][3] + bv1.w, 0.f);
        *(float4*)(sZ + (r0 + i) * 64 + (tx << 2)) = v;
    }
#pragma unroll
    for (int j = 0; j < 4; j++) {
        int idx = (j * 256 + tid) * 4;
        *(float4*)(sW + idx) = *(const float4*)(W2 + idx);
    }
    __syncthreads();

    gemm_tile(sZ, sW, r0, tx, res);
    float4 bv2 = *(const float4*)(b2 + (tx << 2));
#pragma unroll
    for (int i = 0; i < 4; i++) {
        int r = row0 + r0 + i;
        if (r < N_NODES) {
            float4 v;
            v.x = res[i][0] + bv2.x;
            v.y = res[i][1] + bv2.y;
            v.z = res[i][2] + bv2.z;
            v.w = res[i][3] + bv2.w;
            *(float4*)(out + r * 64 + (tx << 2)) = v;
        }
    }
}

// ---------------- mean pool (batch is sorted -> run-length compress atomics)
__global__ __launch_bounds__(256) void pool_kernel(const float* __restrict__ h) {
    const int NPG = 8;
    int grp = blockIdx.x * 4 + (threadIdx.x >> 6);
    int c = threadIdx.x & 63;
    int i0 = grp * NPG;
    if (i0 >= N_NODES) return;
    float acc = 0.f; int cur = -1; int run = 0;
    for (int j = 0; j < NPG; j++) {
        int i = i0 + j;
        if (i >= N_NODES) break;
        int b = g_batch[i];
        if (b != cur) {
            if (cur >= 0) {
                atomicAdd(&g_pool[cur * 64 + c], acc);
                if (c == 0) atomicAdd(&g_cnt[cur], (float)run);
            }
            acc = 0.f; cur = b; run = 0;
        }
        acc += h[i * 64 + c];
        run++;
    }
    if (cur >= 0) {
        atomicAdd(&g_pool[cur * 64 + c], acc);
        if (c == 0) atomicAdd(&g_cnt[cur], (float)run);
    }
}

// ---------------- readout MLP ----------------------------------------------
__global__ __launch_bounds__(64) void readout_kernel(
    const float* __restrict__ mW1, const float* __restrict__ mb1,
    const float* __restrict__ mW2, const float* __restrict__ mb2,
    float* __restrict__ out) {
    __shared__ float p[64], t[64];
    int g = blockIdx.x, c = threadIdx.x;
    float cnt = g_cnt[g];
    if (cnt < 1.f) cnt = 1.f;
    p[c] = g_pool[g * 64 + c] / cnt;
    __syncthreads();
    float a = mb1[c];
#pragma unroll 8
    for (int k = 0; k < 64; k++) a += p[k] * mW1[k * 64 + c];
    t[c] = a > 0.f ? a : 0.f;
    __syncthreads();
    float o = mb2[c];
#pragma unroll 8
    for (int k = 0; k < 64; k++) o += t[k] * mW2[k * 64 + c];
    out[g * 64 + c] = o;
}

// ---------------- launch ----------------------------------------------------
extern "C" void kernel_launch(void* const* d_in, const int* in_sizes, int n_in,
                              void* d_out, int out_size) {
    const float* x   = (const float*)d_in[0];
    const void*  ei  = d_in[1];
    const void*  ba  = d_in[2];
    const float* Ws1 = (const float*)d_in[3];
    const float* bs1 = (const float*)d_in[4];
    const float* Ws2 = (const float*)d_in[5];
    const float* bs2 = (const float*)d_in[6];
    const float* mW1 = (const float*)d_in[7];
    const float* mb1 = (const float*)d_in[8];
    const float* mW2 = (const float*)d_in[9];
    const float* mb2 = (const float*)d_in[10];
    float* out = (float*)d_out;

    float *bufA, *bufB;
    cudaGetSymbolAddress((void**)&bufA, g_bufA);
    cudaGetSymbolAddress((void**)&bufB, g_bufB);

    const int EG = (N_EDGES + 255) / 256;   // 6250
    const int NG = (N_NODES + 255) / 256;   // 391
    const int AG = (N_NODES + 15) / 16;     // 6250
    const int MG = (N_NODES + 63) / 64;     // 1563

    detect_kernel<<<1, 256>>>(ei, ba);
    conv_batch_kernel<<<NG, 256>>>(ba);
    zero_meta_kernel<<<(N_RS + 255) / 256, 256>>>();
    hist_kernel<<<EG, 256>>>(ei);
    scan1_kernel<<<NB, SCAN_B>>>();
    scan2_kernel<<<1, 128>>>();
    scan3_kernel<<<NB, SCAN_B>>>();
    cursor_kernel<<<NG, 256>>>();
    fill_kernel<<<EG, 256>>>(ei);

    const float* h = x;
    for (int l = 0; l < N_LAYERS; l++) {
        agg_kernel<<<AG, 256>>>((const float4*)h, (float4*)bufB);
        mlp_kernel<<<MG, 256>>>(bufB, bufA,
                                Ws1 + l * D * D, bs1 + l * D,
                                Ws2 + l * D * D, bs2 + l * D);
        h = bufA;
    }
    pool_kernel<<<(N_NODES / 8 + 3) / 4, 256>>>(h);
    readout_kernel<<<N_GRAPHS, 64>>>(mW1, mb1, mW2, mb2, out);
}

// round 13
// speedup vs baseline: 1.4941x; 1.1027x over previous
#include <cuda_runtime.h>
#include <cuda_bf16.h>

#define N_NODES 100000
#define N_EDGES 1600000
#define D 64
#define N_LAYERS 5
#define N_GRAPHS 256
#define N_RS (N_NODES + 1)
#define SCAN_B 1024
#define NB ((N_RS + SCAN_B - 1) / SCAN_B)   // 98

typedef unsigned long long ull;
typedef unsigned int uint;

// ---------------- device scratch (static: no allocation at runtime) --------
__device__ __nv_bfloat16 g_hA[N_NODES * D];
__device__ __nv_bfloat16 g_hB[N_NODES * D];
__device__ __nv_bfloat16 g_z[N_NODES * D];
__device__ int   g_srcs[N_EDGES];       // src sorted by dst (CSR payload)
__device__ int   g_batch[N_NODES];
__device__ int   g_rowstart[N_RS];
__device__ int   g_cursor[N_NODES];
__device__ int   g_bsum[NB];
__device__ float g_pool[N_GRAPHS * D];
__device__ float g_cnt[N_GRAPHS];
__device__ int   g_flags[2];            // [0]=edge_index is int64, [1]=batch is int64

// ---------------- packed fp32x2 helpers (Blackwell) -------------------------
__device__ __forceinline__ ull f32x2_fma(ull a, ull b, ull c) {
    ull d;
    asm("fma.rn.f32x2 %0, %1, %2, %3;" : "=l"(d) : "l"(a), "l"(b), "l"(c));
    return d;
}
__device__ __forceinline__ ull f32_dup(float v) {
    ull d;
    asm("mov.b64 %0, {%1, %1};" : "=l"(d) : "f"(v));
    return d;
}
__device__ __forceinline__ void f32x2_unpack(ull a, float& lo, float& hi) {
    asm("mov.b64 {%0, %1}, %2;" : "=f"(lo), "=f"(hi) : "l"(a));
}

// ---------------- bf16 helpers ----------------------------------------------
// bf16 -> fp32 is an exact shift (alu pipe, no cvt)
__device__ __forceinline__ void bf2f(uint u, float& lo, float& hi) {
    lo = __uint_as_float(u << 16);
    hi = __uint_as_float(u & 0xffff0000u);
}
__device__ __forceinline__ uint pack_bf(float lo, float hi) {
    uint r;
    asm("cvt.rn.bf16x2.f32 %0, %1, %2;" : "=r"(r) : "f"(hi), "f"(lo));
    return r;
}
__device__ __forceinline__ void acc_add(float* a, uint4 w) {
    float lo, hi;
    bf2f(w.x, lo, hi); a[0] += lo; a[1] += hi;
    bf2f(w.y, lo, hi); a[2] += lo; a[3] += hi;
    bf2f(w.z, lo, hi); a[4] += lo; a[5] += hi;
    bf2f(w.w, lo, hi); a[6] += lo; a[7] += hi;
}

// ---------------- dtype detection (int64 vs int32) -------------------------
__global__ void detect_kernel(const void* ep, const void* bp) {
    __shared__ int ez, bz;
    if (threadIdx.x == 0) { ez = 0; bz = 0; }
    __syncthreads();
    const int* ew = (const int*)ep;
    if (ew[2 * threadIdx.x + 1] != 0) atomicOr(&ez, 1);
    const int* bw = (const int*)bp;
    if (bw[50001 + 2 * threadIdx.x] != 0) atomicOr(&bz, 1);
    __syncthreads();
    if (threadIdx.x == 0) { g_flags[0] = ez ? 0 : 1; g_flags[1] = bz ? 0 : 1; }
}

__global__ void conv_batch_kernel(const void* p) {
    int i = blockIdx.x * blockDim.x + threadIdx.x;
    if (i >= N_NODES) return;
    g_batch[i] = g_flags[1] ? (int)((const long long*)p)[i] : ((const int*)p)[i];
}

// convert input x (fp32) -> bf16 feature buffer
__global__ void convx_kernel(const float4* __restrict__ x4) {
    int i = blockIdx.x * blockDim.x + threadIdx.x;
    if (i >= N_NODES * D / 4) return;
    float4 v = x4[i];
    uint2 o;
    o.x = pack_bf(v.x, v.y);
    o.y = pack_bf(v.z, v.w);
    ((uint2*)g_hA)[i] = o;
}

// ---------------- CSR build -------------------------------------------------
__global__ void zero_meta_kernel() {
    int i = blockIdx.x * blockDim.x + threadIdx.x;
    if (i < N_RS)          g_rowstart[i] = 0;
    if (i < N_GRAPHS * D)  g_pool[i] = 0.f;
    if (i < N_GRAPHS)      g_cnt[i] = 0.f;
}

__global__ void hist_kernel(const void* p) {
    int e = blockIdx.x * blockDim.x + threadIdx.x;
    if (e >= N_EDGES) return;
    int d = g_flags[0] ? (int)((const long long*)p)[N_EDGES + e]
                       : ((const int*)p)[N_EDGES + e];
    atomicAdd(&g_rowstart[d + 1], 1);
}

__global__ __launch_bounds__(SCAN_B) void scan1_kernel() {
    __shared__ int sm[SCAN_B];
    int i = blockIdx.x * SCAN_B + threadIdx.x;
    sm[threadIdx.x] = (i < N_RS) ? g_rowstart[i] : 0;
    __syncthreads();
    for (int off = 1; off < SCAN_B; off <<= 1) {
        int t = 0;
        if ((int)threadIdx.x >= off) t = sm[threadIdx.x - off];
        __syncthreads();
        sm[threadIdx.x] += t;
        __syncthreads();
    }
    if (i < N_RS) g_rowstart[i] = sm[threadIdx.x];
    if (threadIdx.x == SCAN_B - 1) g_bsum[blockIdx.x] = sm[SCAN_B - 1];
}

__global__ void scan2_kernel() {
    __shared__ int s[128];
    int t = threadIdx.x;
    s[t] = (t < NB) ? g_bsum[t] : 0;
    __syncthreads();
    if (t == 0) {
        int run = 0;
        for (int i = 0; i < NB; i++) { int v = s[i]; s[i] = run; run += v; }
    }
    __syncthreads();
    if (t < NB) g_bsum[t] = s[t];
}

__global__ __launch_bounds__(SCAN_B) void scan3_kernel() {
    int i = blockIdx.x * SCAN_B + threadIdx.x;
    if (i < N_RS) {
        int v = g_rowstart[i] + g_bsum[blockIdx.x];
        g_rowstart[i] = v;
        if (i < N_NODES) g_cursor[i] = v;   // cursor init folded in
    }
}

__global__ void fill_kernel(const void* p) {
    int e = blockIdx.x * blockDim.x + threadIdx.x;
    if (e >= N_EDGES) return;
    int s, d;
    if (g_flags[0]) {
        const long long* q = (const long long*)p;
        s = (int)q[e]; d = (int)q[N_EDGES + e];
    } else {
        const int* q = (const int*)p;
        s = q[e]; d = q[N_EDGES + e];
    }
    int pos = atomicAdd(&g_cursor[d], 1);
    g_srcs[pos] = s;
}

// ---------------- GIN aggregation (bf16 rows, fp32 accumulate) --------------
// 8 threads per node, each owns a 16B chunk (8 bf16). Row = 128B.
__global__ __launch_bounds__(256) void agg_kernel(const uint4* __restrict__ h4,
                                                  uint4* __restrict__ z4) {
    int node = blockIdx.x * 32 + (threadIdx.x >> 3);
    int c = threadIdx.x & 7;
    if (node >= N_NODES) return;
    float a[8];
    {
        uint4 v = h4[node * 8 + c];
        float lo, hi;
        bf2f(v.x, lo, hi); a[0] = lo; a[1] = hi;
        bf2f(v.y, lo, hi); a[2] = lo; a[3] = hi;
        bf2f(v.z, lo, hi); a[4] = lo; a[5] = hi;
        bf2f(v.w, lo, hi); a[6] = lo; a[7] = hi;
    }
    int s = g_rowstart[node];
    int e = g_rowstart[node + 1];
    int i = s;
    for (; i + 2 <= e; i += 2) {
        int s0 = g_srcs[i], s1 = g_srcs[i + 1];
        uint4 w0 = __ldg(&h4[s0 * 8 + c]);
        uint4 w1 = __ldg(&h4[s1 * 8 + c]);
        acc_add(a, w0);
        acc_add(a, w1);
    }
    if (i < e) acc_add(a, __ldg(&h4[g_srcs[i] * 8 + c]));

    uint4 o;
    o.x = pack_bf(a[0], a[1]);
    o.y = pack_bf(a[2], a[3]);
    o.z = pack_bf(a[4], a[5]);
    o.w = pack_bf(a[6], a[7]);
    z4[node * 8 + c] = o;
}

// ---------------- 64x64 register-blocked GEMM tile (packed f32x2) -----------
__device__ __forceinline__ void gemm_tile(const float* __restrict__ sZ,
                                          const float* __restrict__ sW,
                                          int r0, int tx, float out[4][4]) {
    ull acc[4][2];
#pragma unroll
    for (int i = 0; i < 4; i++) { acc[i][0] = 0ull; acc[i][1] = 0ull; }
#pragma unroll
    for (int k0 = 0; k0 < 64; k0 += 4) {
        float4 zq[4];
#pragma unroll
        for (int i = 0; i < 4; i++)
            zq[i] = *(const float4*)(sZ + (r0 + i) * 64 + k0);
#pragma unroll
        for (int k = 0; k < 4; k++) {
            ulonglong2 wv = *(const ulonglong2*)(sW + (k0 + k) * 64 + (tx << 2));
#pragma unroll
            for (int i = 0; i < 4; i++) {
                float zk = (k == 0) ? zq[i].x : (k == 1) ? zq[i].y
                         : (k == 2) ? zq[i].z : zq[i].w;
                ull zd = f32_dup(zk);
                acc[i][0] = f32x2_fma(zd, wv.x, acc[i][0]);
                acc[i][1] = f32x2_fma(zd, wv.y, acc[i][1]);
            }
        }
    }
#pragma unroll
    for (int i = 0; i < 4; i++) {
        f32x2_unpack(acc[i][0], out[i][0], out[i][1]);
        f32x2_unpack(acc[i][1], out[i][2], out[i][3]);
    }
}

// ---------------- fused MLP: out = relu(z@W1 + b1) @ W2 + b2 ---------------
// z in bf16 (unpacked to fp32 smem), weights/compute fp32, out stored bf16.
__global__ __launch_bounds__(256) void mlp_kernel(
    const uint4* __restrict__ zin4, __nv_bfloat16* __restrict__ out,
    const float* __restrict__ W1, const float* __restrict__ b1,
    const float* __restrict__ W2, const float* __restrict__ b2) {
    __shared__ float sZ[64 * 64];   // z tile [r][k]; reused for hidden act
    __shared__ float sW[64 * 64];   // weights [k][c]
    int tid = threadIdx.x;
    int row0 = blockIdx.x * 64;

    // load bf16 z tile (512 uint4 per tile), unpack to fp32 smem
#pragma unroll
    for (int j = 0; j < 2; j++) {
        int idx = j * 256 + tid;     // uint4 index within tile (8 per row)
        int r = idx >> 3;
        uint4 v = (row0 + r < N_NODES) ? zin4[row0 * 8 + idx]
                                       : make_uint4(0, 0, 0, 0);
        float* dst = sZ + idx * 8;
        float lo, hi;
        bf2f(v.x, lo, hi); dst[0] = lo; dst[1] = hi;
        bf2f(v.y, lo, hi); dst[2] = lo; dst[3] = hi;
        bf2f(v.z, lo, hi); dst[4] = lo; dst[5] = hi;
        bf2f(v.w, lo, hi); dst[6] = lo; dst[7] = hi;
    }
#pragma unroll
    for (int j = 0; j < 4; j++) {
        int idx = (j * 256 + tid) * 4;
        *(float4*)(sW + idx) = *(const float4*)(W1 + idx);
    }
    __syncthreads();

    int ty = tid >> 4, tx = tid & 15;
    int r0 = ty << 2;
    float res[4][4];
    gemm_tile(sZ, sW, r0, tx, res);
    float4 bv1 = *(const float4*)(b1 + (tx << 2));
    __syncthreads();   // all reads of sZ/sW done
#pragma unroll
    for (int i = 0; i < 4; i++) {
        float4 v;
        v.x = fmaxf(res[i][0] + bv1.x, 0.f);
        v.y = fmaxf(res[i][1] + bv1.y, 0.f);
        v.z = fmaxf(res[i][2] + bv1.z, 0.f);
        v.w = fmaxf(res[i][3] + bv1.w, 0.f);
        *(float4*)(sZ + (r0 + i) * 64 + (tx << 2)) = v;
    }
#pragma unroll
    for (int j = 0; j < 4; j++) {
        int idx = (j * 256 + tid) * 4;
        *(float4*)(sW + idx) = *(const float4*)(W2 + idx);
    }
    __syncthreads();

    gemm_tile(sZ, sW, r0, tx, res);
    float4 bv2 = *(const float4*)(b2 + (tx << 2));
#pragma unroll
    for (int i = 0; i < 4; i++) {
        int r = row0 + r0 + i;
        if (r < N_NODES) {
            uint2 o;
            o.x = pack_bf(res[i][0] + bv2.x, res[i][1] + bv2.y);
            o.y = pack_bf(res[i][2] + bv2.z, res[i][3] + bv2.w);
            *(uint2*)(out + r * 64 + (tx << 2)) = o;
        }
    }
}

// ---------------- mean pool (batch sorted -> run-length compressed atomics)
__global__ __launch_bounds__(256) void pool_kernel(const __nv_bfloat16* __restrict__ h) {
    const int NPG = 8;
    int grp = blockIdx.x * 4 + (threadIdx.x >> 6);
    int c = threadIdx.x & 63;
    int i0 = grp * NPG;
    if (i0 >= N_NODES) return;
    float acc = 0.f; int cur = -1; int run = 0;
    for (int j = 0; j < NPG; j++) {
        int i = i0 + j;
        if (i >= N_NODES) break;
        int b = g_batch[i];
        if (b != cur) {
            if (cur >= 0) {
                atomicAdd(&g_pool[cur * 64 + c], acc);
                if (c == 0) atomicAdd(&g_cnt[cur], (float)run);
            }
            acc = 0.f; cur = b; run = 0;
        }
        acc += __bfloat162float(h[i * 64 + c]);
        run++;
    }
    if (cur >= 0) {
        atomicAdd(&g_pool[cur * 64 + c], acc);
        if (c == 0) atomicAdd(&g_cnt[cur], (float)run);
    }
}

// ---------------- readout MLP ----------------------------------------------
__global__ __launch_bounds__(64) void readout_kernel(
    const float* __restrict__ mW1, const float* __restrict__ mb1,
    const float* __restrict__ mW2, const float* __restrict__ mb2,
    float* __restrict__ out) {
    __shared__ float p[64], t[64];
    int g = blockIdx.x, c = threadIdx.x;
    float cnt = g_cnt[g];
    if (cnt < 1.f) cnt = 1.f;
    p[c] = g_pool[g * 64 + c] / cnt;
    __syncthreads();
    float a = mb1[c];
#pragma unroll 8
    for (int k = 0; k < 64; k++) a += p[k] * mW1[k * 64 + c];
    t[c] = a > 0.f ? a : 0.f;
    __syncthreads();
    float o = mb2[c];
#pragma unroll 8
    for (int k = 0; k < 64; k++) o += t[k] * mW2[k * 64 + c];
    out[g * 64 + c] = o;
}

// ---------------- launch ----------------------------------------------------
extern "C" void kernel_launch(void* const* d_in, const int* in_sizes, int n_in,
                              void* d_out, int out_size) {
    const float* x   = (const float*)d_in[0];
    const void*  ei  = d_in[1];
    const void*  ba  = d_in[2];
    const float* Ws1 = (const float*)d_in[3];
    const float* bs1 = (const float*)d_in[4];
    const float* Ws2 = (const float*)d_in[5];
    const float* bs2 = (const float*)d_in[6];
    const float* mW1 = (const float*)d_in[7];
    const float* mb1 = (const float*)d_in[8];
    const float* mW2 = (const float*)d_in[9];
    const float* mb2 = (const float*)d_in[10];
    float* out = (float*)d_out;

    __nv_bfloat16 *hA, *hB, *z;
    cudaGetSymbolAddress((void**)&hA, g_hA);
    cudaGetSymbolAddress((void**)&hB, g_hB);
    cudaGetSymbolAddress((void**)&z,  g_z);

    const int EG = (N_EDGES + 255) / 256;   // 6250
    const int NG = (N_NODES + 255) / 256;   // 391
    const int AG = (N_NODES + 31) / 32;     // 3125
    const int MG = (N_NODES + 63) / 64;     // 1563
    const int XG = (N_NODES * D / 4 + 255) / 256;

    detect_kernel<<<1, 256>>>(ei, ba);
    conv_batch_kernel<<<NG, 256>>>(ba);
    convx_kernel<<<XG, 256>>>((const float4*)x);
    zero_meta_kernel<<<(N_RS + 255) / 256, 256>>>();
    hist_kernel<<<EG, 256>>>(ei);
    scan1_kernel<<<NB, SCAN_B>>>();
    scan2_kernel<<<1, 128>>>();
    scan3_kernel<<<NB, SCAN_B>>>();
    fill_kernel<<<EG, 256>>>(ei);

    // ping-pong: hA -> hB -> hA -> hB -> hA -> hB
    const __nv_bfloat16* hin = hA;
    __nv_bfloat16* hout = hB;
    for (int l = 0; l < N_LAYERS; l++) {
        agg_kernel<<<AG, 256>>>((const uint4*)hin, (uint4*)z);
        mlp_kernel<<<MG, 256>>>((const uint4*)z, hout,
                                Ws1 + l * D * D, bs1 + l * D,
                                Ws2 + l * D * D, bs2 + l * D);
        const __nv_bfloat16* tmp = hin;
        hin = hout;
        hout = (__nv_bfloat16*)tmp;
    }
    pool_kernel<<<(N_NODES / 8 + 3) / 4, 256>>>(hin);
    readout_kernel<<<N_GRAPHS, 64>>>(mW1, mb1, mW2, mb2, out);
}